// round 14
// baseline (speedup 1.0000x reference)
#include <cuda_runtime.h>
#include <cuda_fp16.h>
#include <mma.h>
#include <math.h>
#include <stdint.h>

using namespace nvcuda;

// Problem constants: B=4, S=2048, D=1024, H=2048, O=1024, E=8, K=2
#define TB   8192
#define DD   1024
#define HH   2048
#define OO   1024
#define NE   8
#define NR   16384

// ---------------- scratch (__device__ globals; referenced ONLY inside kernels)
__device__ int    g_cnt[NE];
__device__ int    g_off[NE];
__device__ int    g_fill[NE];
__device__ int    g_tok_e[TB * 2];
__device__ float  g_tok_p[TB * 2];
__device__ int    g_row_tok[NR];
__device__ float  g_row_gate[NR];
__device__ __half g_xh[(size_t)TB * DD];        // 16.8 MB x fp16
__device__ __half g_w1h[(size_t)NE * DD * HH];  // 33.5 MB w1 fp16 [E][D][H]
__device__ __half g_w2h[(size_t)NE * HH * OO];  // 33.5 MB w2 fp16 [E][H][O]
__device__ __half g_hbuf[(size_t)NR * HH];      // 67 MB hidden activations fp16

// smem geometry: CTA tile 128x256, KC=64
#define KC     64
#define ROWP   72            // A row pitch (halves): 64 data + 8 pad
#define BROWP  264           // B row pitch (halves): 256 data + 8 pad
#define A_STAGE (128 * ROWP)            // 9216 halves = 18432 B
#define B_STAGE (KC * BROWP)            // 16896 halves = 33792 B
#define OFF_AB   1024
#define OFF_BB   (OFF_AB + 2 * A_STAGE * 2)
#define SMEM_DYN (OFF_BB + 2 * B_STAGE * 2)   // 1024 + 36864 + 67584 = 105472 B

// ---------------- cp.async helpers ----------------
__device__ __forceinline__ uint32_t smem_u32(const void* p) {
    uint32_t a;
    asm("{ .reg .u64 t; cvta.to.shared.u64 t, %1; cvt.u32.u64 %0, t; }" : "=r"(a) : "l"(p));
    return a;
}
__device__ __forceinline__ void cpa16(uint32_t dst, const void* src) {
    asm volatile("cp.async.cg.shared.global [%0], [%1], 16;" :: "r"(dst), "l"(src));
}
#define CP_COMMIT() asm volatile("cp.async.commit_group;" ::: "memory")
#define CP_WAIT0()  asm volatile("cp.async.wait_group 0;" ::: "memory")

// ---------------- small kernels ----------------
__global__ void zero_kernel() {
    int i = threadIdx.x;
    if (i < NE) { g_cnt[i] = 0; g_fill[i] = 0; }
}

__global__ __launch_bounds__(256) void zero_out_kernel(float* __restrict__ out) {
    size_t i = (size_t)(blockIdx.x * blockDim.x + threadIdx.x) * 4;
    *(float4*)(out + i) = make_float4(0.f, 0.f, 0.f, 0.f);
}

__global__ __launch_bounds__(256) void gate_kernel(
    const float* __restrict__ x, const float* __restrict__ gw, const float* __restrict__ gb)
{
    int t = blockIdx.x, tid = threadIdx.x;
    int w = tid >> 5, lane = tid & 31;
    const float* xr = x + (size_t)t * DD;
    const float* gr = gw + (size_t)w * DD;
    float s = 0.f;
    #pragma unroll 8
    for (int j = lane; j < DD; j += 32) s += xr[j] * gr[j];
    #pragma unroll
    for (int o = 16; o > 0; o >>= 1) s += __shfl_xor_sync(0xFFFFFFFFu, s, o);
    __shared__ float lg[NE];
    if (lane == 0) lg[w] = s + gb[w];
    __syncthreads();
    if (tid == 0) {
        float mx = lg[0];
        #pragma unroll
        for (int e = 1; e < NE; e++) mx = fmaxf(mx, lg[e]);
        float ex[NE]; float den = 0.f;
        #pragma unroll
        for (int e = 0; e < NE; e++) { ex[e] = expf(lg[e] - mx); den += ex[e]; }
        int i0 = 0;
        #pragma unroll
        for (int e = 1; e < NE; e++) if (lg[e] > lg[i0]) i0 = e;
        int i1 = (i0 == 0) ? 1 : 0;
        #pragma unroll
        for (int e = 0; e < NE; e++) if (e != i0 && e != i1 && lg[e] > lg[i1]) i1 = e;
        float inv = 1.f / den;
        g_tok_e[t * 2 + 0] = i0; g_tok_p[t * 2 + 0] = ex[i0] * inv;
        g_tok_e[t * 2 + 1] = i1; g_tok_p[t * 2 + 1] = ex[i1] * inv;
        atomicAdd(&g_cnt[i0], 1);
        atomicAdd(&g_cnt[i1], 1);
    }
}

__global__ void offsets_kernel() {
    if (threadIdx.x == 0) {
        int s = 0;
        #pragma unroll
        for (int e = 0; e < NE; e++) { g_off[e] = s; s += g_cnt[e]; }
    }
}

__global__ void scatter_kernel() {
    int t = blockIdx.x * blockDim.x + threadIdx.x;
    if (t >= TB) return;
    #pragma unroll
    for (int k = 0; k < 2; k++) {
        int e = g_tok_e[t * 2 + k];
        int pos = atomicAdd(&g_fill[e], 1);
        int r = g_off[e] + pos;
        g_row_tok[r] = t;
        g_row_gate[r] = g_tok_p[t * 2 + k];
    }
}

// ---------------- fp32 -> fp16 conversion (globals referenced internally) ---
__global__ __launch_bounds__(256) void cvt_x_kernel(const float* __restrict__ x) {
    size_t i = (size_t)(blockIdx.x * blockDim.x + threadIdx.x) * 8;
    float4 a = *(const float4*)(x + i);
    float4 b = *(const float4*)(x + i + 4);
    __half2 h[4] = { __floats2half2_rn(a.x, a.y), __floats2half2_rn(a.z, a.w),
                     __floats2half2_rn(b.x, b.y), __floats2half2_rn(b.z, b.w) };
    *(uint4*)(g_xh + i) = *(uint4*)h;
}
__global__ __launch_bounds__(256) void cvt_w1_kernel(const float* __restrict__ w) {
    size_t i = (size_t)(blockIdx.x * blockDim.x + threadIdx.x) * 8;
    float4 a = *(const float4*)(w + i);
    float4 b = *(const float4*)(w + i + 4);
    __half2 h[4] = { __floats2half2_rn(a.x, a.y), __floats2half2_rn(a.z, a.w),
                     __floats2half2_rn(b.x, b.y), __floats2half2_rn(b.z, b.w) };
    *(uint4*)(g_w1h + i) = *(uint4*)h;
}
__global__ __launch_bounds__(256) void cvt_w2_kernel(const float* __restrict__ w) {
    size_t i = (size_t)(blockIdx.x * blockDim.x + threadIdx.x) * 8;
    float4 a = *(const float4*)(w + i);
    float4 b = *(const float4*)(w + i + 4);
    __half2 h[4] = { __floats2half2_rn(a.x, a.y), __floats2half2_rn(a.z, a.w),
                     __floats2half2_rn(b.x, b.y), __floats2half2_rn(b.z, b.w) };
    *(uint4*)(g_w2h + i) = *(uint4*)h;
}

// ---------------- cp.async WMMA GEMM mainloop -------------------------------
// CTA tile 128x256, 8 warps (2m x 4n), warp tile 64x64, KC=64, double-buffered,
// ONE barrier per chunk: wait(ch) -> barrier -> issue(ch+1) -> compute(ch).
template<int SK, int NCHUNKS>
__device__ __forceinline__ void gemm_async(
    const __half* __restrict__ Asrc, const int* srcrow,
    const __half* __restrict__ Bsrc, int SN,
    char* DSM, int tid,
    wmma::fragment<wmma::accumulator, 16, 16, 16, float> (&acc)[4][4])
{
    int wid = tid >> 5;
    int warp_m = wid >> 2, warp_n = wid & 3;

    __half* AbP[2] = { (__half*)(DSM + OFF_AB), (__half*)(DSM + OFF_AB) + A_STAGE };
    __half* BbP[2] = { (__half*)(DSM + OFF_BB), (__half*)(DSM + OFF_BB) + B_STAGE };
    uint32_t AbU[2] = { smem_u32(AbP[0]), smem_u32(AbP[1]) };
    uint32_t BbU[2] = { smem_u32(BbP[0]), smem_u32(BbP[1]) };

    // per-thread cp.async mappings: 4 A + 8 B 16B-copies per stage
    const __half* AgB[4]; uint32_t AdO[4];
    const __half* BgB[8]; uint32_t BdO[8];
    #pragma unroll
    for (int l = 0; l < 4; l++) {
        int f = l * 256 + tid;
        int ar = f >> 3, as = f & 7;          // A: 128 rows x 8 segs (16B)
        AgB[l] = Asrc + (size_t)srcrow[ar] * SK + as * 8;
        AdO[l] = ar * ROWP + as * 8;
    }
    #pragma unroll
    for (int l = 0; l < 8; l++) {
        int f = l * 256 + tid;
        int br = f >> 5, bs = f & 31;         // B: 64 rows x 32 segs (16B)
        BgB[l] = Bsrc + (size_t)br * SN + bs * 8;
        BdO[l] = br * BROWP + bs * 8;
    }

    // prologue: stage 0
    #pragma unroll
    for (int l = 0; l < 4; l++) cpa16(AbU[0] + AdO[l] * 2, AgB[l]);
    #pragma unroll
    for (int l = 0; l < 8; l++) cpa16(BbU[0] + BdO[l] * 2, BgB[l]);
    CP_COMMIT();

    for (int ch = 0; ch < NCHUNKS; ch++) {
        int cur = ch & 1;
        CP_WAIT0();
        __syncthreads();
        if (ch + 1 < NCHUNKS) {
            int nxt = cur ^ 1;
            #pragma unroll
            for (int l = 0; l < 4; l++)
                cpa16(AbU[nxt] + AdO[l] * 2, AgB[l] + (ch + 1) * KC);
            #pragma unroll
            for (int l = 0; l < 8; l++)
                cpa16(BbU[nxt] + BdO[l] * 2, BgB[l] + (size_t)(ch + 1) * KC * SN);
        }
        CP_COMMIT();
        const __half* Ac = AbP[cur];
        const __half* Bc = BbP[cur];
        #pragma unroll
        for (int kf = 0; kf < KC; kf += 16) {
            wmma::fragment<wmma::matrix_a, 16, 16, 16, __half, wmma::row_major> af[4];
            #pragma unroll
            for (int i = 0; i < 4; i++)
                wmma::load_matrix_sync(af[i], Ac + (warp_m * 64 + i * 16) * ROWP + kf, ROWP);
            #pragma unroll
            for (int j = 0; j < 4; j++) {
                wmma::fragment<wmma::matrix_b, 16, 16, 16, __half, wmma::row_major> bf;
                wmma::load_matrix_sync(bf, Bc + kf * BROWP + warp_n * 64 + j * 16, BROWP);
                #pragma unroll
                for (int i = 0; i < 4; i++)
                    wmma::mma_sync(acc[i][j], af[i], bf, acc[i][j]);
            }
        }
    }
    __syncthreads();           // protect smem reuse (epilogue stg aliases A)
}

// ---------------- GEMM1: hbuf = relu(gather(xh) @ w1h[e] + b1[e]) -----------
__global__ __launch_bounds__(256) void gemm1_wmma(const float* __restrict__ b1)
{
    extern __shared__ __align__(16) char DSM[];
    int* toks = (int*)DSM;

    int e = blockIdx.z;
    int cnt = g_cnt[e];
    int m0 = blockIdx.y * 128;
    if (m0 >= cnt) return;
    int n0 = blockIdx.x * 256;
    int base = g_off[e];

    int tid = threadIdx.x, wid = tid >> 5, lane = tid & 31;
    int warp_m = wid >> 2, warp_n = wid & 3;

    if (tid < 128) {
        int m = m0 + tid;
        toks[tid] = g_row_tok[base + ((m < cnt) ? m : 0)];
    }
    __syncthreads();

    wmma::fragment<wmma::accumulator, 16, 16, 16, float> acc[4][4];
    #pragma unroll
    for (int i = 0; i < 4; i++)
        #pragma unroll
        for (int j = 0; j < 4; j++) wmma::fill_fragment(acc[i][j], 0.f);

    gemm_async<DD, DD / KC>(g_xh, toks, g_w1h + (size_t)e * DD * HH + n0, HH,
                            DSM, tid, acc);

    // epilogue: stage via smem (aliases A pipeline region), +bias, relu, fp16
    float* stg = (float*)(DSM + OFF_AB) + wid * 320;
    int erow = lane >> 1, ec8 = (lane & 1) * 8;
    #pragma unroll
    for (int i = 0; i < 4; i++) {
        #pragma unroll
        for (int j = 0; j < 4; j++) {
            wmma::store_matrix_sync(stg, acc[i][j], 20, wmma::mem_row_major);
            __syncwarp();
            int gr = m0 + warp_m * 64 + i * 16 + erow;
            int gc = n0 + warp_n * 64 + j * 16 + ec8;
            if (gr < cnt) {
                __half h[8];
                #pragma unroll
                for (int t2 = 0; t2 < 8; t2++)
                    h[t2] = __float2half_rn(fmaxf(stg[erow * 20 + ec8 + t2]
                                                  + b1[(size_t)e * HH + gc + t2], 0.f));
                *(uint4*)(g_hbuf + (size_t)(base + gr) * HH + gc) = *(uint4*)h;
            }
            __syncwarp();
        }
    }
}

// ---------------- GEMM2: out[tok] += (hbuf @ w2h[e] + b2[e]) * gate ---------
__global__ __launch_bounds__(256) void gemm2_wmma(const float* __restrict__ b2,
                                                  float* __restrict__ out)
{
    extern __shared__ __align__(16) char DSM[];
    int* rows = (int*)DSM;

    int e = blockIdx.z;
    int cnt = g_cnt[e];
    int m0 = blockIdx.y * 128;
    if (m0 >= cnt) return;
    int n0 = blockIdx.x * 256;
    int base = g_off[e];

    int tid = threadIdx.x, wid = tid >> 5, lane = tid & 31;
    int warp_m = wid >> 2, warp_n = wid & 3;

    if (tid < 128) {
        int m = m0 + tid; if (m >= cnt) m = cnt - 1;
        rows[tid] = base + m;
    }
    __syncthreads();

    wmma::fragment<wmma::accumulator, 16, 16, 16, float> acc[4][4];
    #pragma unroll
    for (int i = 0; i < 4; i++)
        #pragma unroll
        for (int j = 0; j < 4; j++) wmma::fill_fragment(acc[i][j], 0.f);

    gemm_async<HH, HH / KC>(g_hbuf, rows, g_w2h + (size_t)e * HH * OO + n0, OO,
                            DSM, tid, acc);

    // epilogue: stage, +bias, * gate, atomic accumulate into out[token]
    float* stg = (float*)(DSM + OFF_AB) + wid * 320;
    int erow = lane >> 1, ec8 = (lane & 1) * 8;
    #pragma unroll
    for (int i = 0; i < 4; i++) {
        #pragma unroll
        for (int j = 0; j < 4; j++) {
            wmma::store_matrix_sync(stg, acc[i][j], 20, wmma::mem_row_major);
            __syncwarp();
            int gr = m0 + warp_m * 64 + i * 16 + erow;
            int gc = n0 + warp_n * 64 + j * 16 + ec8;
            if (gr < cnt) {
                int r = base + gr;
                int tok = g_row_tok[r];
                float gate = g_row_gate[r];
                float* dst = out + (size_t)tok * OO + gc;
                #pragma unroll
                for (int t2 = 0; t2 < 8; t2++)
                    atomicAdd(dst + t2,
                              (stg[erow * 20 + ec8 + t2]
                               + b2[(size_t)e * OO + gc + t2]) * gate);
            }
            __syncwarp();
        }
    }
}

// ---------------- launch ----------------
extern "C" void kernel_launch(void* const* d_in, const int* in_sizes, int n_in,
                              void* d_out, int out_size)
{
    const float* x  = (const float*)d_in[0];
    const float* gw = (const float*)d_in[1];
    const float* gb = (const float*)d_in[2];
    const float* w1 = (const float*)d_in[3];
    const float* b1 = (const float*)d_in[4];
    const float* w2 = (const float*)d_in[5];
    const float* b2 = (const float*)d_in[6];
    float* out = (float*)d_out;

    static int attr_done = 0;
    if (!attr_done) {
        cudaFuncSetAttribute(gemm1_wmma, cudaFuncAttributeMaxDynamicSharedMemorySize, SMEM_DYN);
        cudaFuncSetAttribute(gemm2_wmma, cudaFuncAttributeMaxDynamicSharedMemorySize, SMEM_DYN);
        attr_done = 1;
    }

    zero_kernel<<<1, 32>>>();
    gate_kernel<<<TB, 256>>>(x, gw, gb);
    offsets_kernel<<<1, 1>>>();
    scatter_kernel<<<TB / 256, 256>>>();
    cvt_x_kernel<<<TB * DD / 8 / 256, 256>>>(x);
    cvt_w1_kernel<<<NE * DD * HH / 8 / 256, 256>>>(w1);
    cvt_w2_kernel<<<NE * HH * OO / 8 / 256, 256>>>(w2);
    zero_out_kernel<<<TB * OO / 4 / 256, 256>>>(out);
    gemm1_wmma<<<dim3(HH / 256, NR / 128, NE), 256, SMEM_DYN>>>(b1);
    gemm2_wmma<<<dim3(OO / 256, NR / 128, NE), 256, SMEM_DYN>>>(b2, out);
}

// round 15
// speedup vs baseline: 1.0361x; 1.0361x over previous
#include <cuda_runtime.h>
#include <cuda_fp16.h>
#include <mma.h>
#include <math.h>
#include <stdint.h>

using namespace nvcuda;

// Problem constants: B=4, S=2048, D=1024, H=2048, O=1024, E=8, K=2
#define TB   8192
#define DD   1024
#define HH   2048
#define OO   1024
#define NE   8
#define NR   16384

// ---------------- scratch (__device__ globals; referenced ONLY inside kernels)
__device__ int    g_cnt[NE];
__device__ int    g_off[NE];
__device__ int    g_fill[NE];
__device__ int    g_tok_e[TB * 2];
__device__ float  g_tok_p[TB * 2];
__device__ int    g_row_tok[NR];
__device__ float  g_row_gate[NR];
__device__ __half g_xh[(size_t)TB * DD];        // 16.8 MB x fp16
__device__ __half g_w1h[(size_t)NE * DD * HH];  // 33.5 MB w1 fp16 [E][D][H]
__device__ __half g_w2h[(size_t)NE * HH * OO];  // 33.5 MB w2 fp16 [E][H][O]
__device__ __half g_hbuf[(size_t)NR * HH];      // 67 MB hidden activations fp16

// smem geometry: CTA tile 128x128, KC=64 (R13-proven)
#define KC     64
#define ROWP   72            // A row pitch (halves): 64 data + 8 pad
#define BROWP  136           // B row pitch (halves): 128 data + 8 pad
#define A_STAGE (128 * ROWP)            // 9216 halves = 18432 B
#define B_STAGE (KC * BROWP)            // 8704 halves  = 17408 B
#define OFF_AB   1024
#define OFF_BB   (OFF_AB + 2 * A_STAGE * 2)
#define SMEM_DYN (OFF_BB + 2 * B_STAGE * 2)   // 72704 B -> 2 CTAs/SM

// ---------------- cp.async helpers ----------------
__device__ __forceinline__ uint32_t smem_u32(const void* p) {
    uint32_t a;
    asm("{ .reg .u64 t; cvta.to.shared.u64 t, %1; cvt.u32.u64 %0, t; }" : "=r"(a) : "l"(p));
    return a;
}
__device__ __forceinline__ void cpa16(uint32_t dst, const void* src) {
    asm volatile("cp.async.cg.shared.global [%0], [%1], 16;" :: "r"(dst), "l"(src));
}
#define CP_COMMIT() asm volatile("cp.async.commit_group;" ::: "memory")
#define CP_WAIT0()  asm volatile("cp.async.wait_group 0;" ::: "memory")

// ---------------- small kernels ----------------
__global__ void zero_kernel() {
    int i = threadIdx.x;
    if (i < NE) { g_cnt[i] = 0; g_fill[i] = 0; }
}

__global__ __launch_bounds__(256) void zero_out_kernel(float* __restrict__ out) {
    size_t i = (size_t)(blockIdx.x * blockDim.x + threadIdx.x) * 4;
    *(float4*)(out + i) = make_float4(0.f, 0.f, 0.f, 0.f);
}

// gate + fused x fp32->fp16 conversion (x row is L1-resident here)
__global__ __launch_bounds__(256) void gate_kernel(
    const float* __restrict__ x, const float* __restrict__ gw, const float* __restrict__ gb)
{
    int t = blockIdx.x, tid = threadIdx.x;
    int w = tid >> 5, lane = tid & 31;
    const float* xr = x + (size_t)t * DD;
    const float* gr = gw + (size_t)w * DD;
    float s = 0.f;
    #pragma unroll 8
    for (int j = lane; j < DD; j += 32) s += xr[j] * gr[j];
    #pragma unroll
    for (int o = 16; o > 0; o >>= 1) s += __shfl_xor_sync(0xFFFFFFFFu, s, o);
    __shared__ float lg[NE];
    if (lane == 0) lg[w] = s + gb[w];

    // fused conversion: 4 floats per thread
    {
        int j = tid * 4;
        float4 v = *(const float4*)(xr + j);
        __half2 h0 = __floats2half2_rn(v.x, v.y);
        __half2 h1 = __floats2half2_rn(v.z, v.w);
        uint2 u;
        u.x = *(uint32_t*)&h0; u.y = *(uint32_t*)&h1;
        *(uint2*)(g_xh + (size_t)t * DD + j) = u;
    }
    __syncthreads();
    if (tid == 0) {
        float mx = lg[0];
        #pragma unroll
        for (int e = 1; e < NE; e++) mx = fmaxf(mx, lg[e]);
        float ex[NE]; float den = 0.f;
        #pragma unroll
        for (int e = 0; e < NE; e++) { ex[e] = expf(lg[e] - mx); den += ex[e]; }
        int i0 = 0;
        #pragma unroll
        for (int e = 1; e < NE; e++) if (lg[e] > lg[i0]) i0 = e;
        int i1 = (i0 == 0) ? 1 : 0;
        #pragma unroll
        for (int e = 0; e < NE; e++) if (e != i0 && e != i1 && lg[e] > lg[i1]) i1 = e;
        float inv = 1.f / den;
        g_tok_e[t * 2 + 0] = i0; g_tok_p[t * 2 + 0] = ex[i0] * inv;
        g_tok_e[t * 2 + 1] = i1; g_tok_p[t * 2 + 1] = ex[i1] * inv;
        atomicAdd(&g_cnt[i0], 1);
        atomicAdd(&g_cnt[i1], 1);
    }
}

__global__ void offsets_kernel() {
    if (threadIdx.x == 0) {
        int s = 0;
        #pragma unroll
        for (int e = 0; e < NE; e++) { g_off[e] = s; s += g_cnt[e]; }
    }
}

__global__ void scatter_kernel() {
    int t = blockIdx.x * blockDim.x + threadIdx.x;
    if (t >= TB) return;
    #pragma unroll
    for (int k = 0; k < 2; k++) {
        int e = g_tok_e[t * 2 + k];
        int pos = atomicAdd(&g_fill[e], 1);
        int r = g_off[e] + pos;
        g_row_tok[r] = t;
        g_row_gate[r] = g_tok_p[t * 2 + k];
    }
}

// ---------------- fp32 -> fp16 weight conversion ----------------------------
__global__ __launch_bounds__(256) void cvt_w1_kernel(const float* __restrict__ w) {
    size_t i = (size_t)(blockIdx.x * blockDim.x + threadIdx.x) * 8;
    float4 a = *(const float4*)(w + i);
    float4 b = *(const float4*)(w + i + 4);
    __half2 h[4] = { __floats2half2_rn(a.x, a.y), __floats2half2_rn(a.z, a.w),
                     __floats2half2_rn(b.x, b.y), __floats2half2_rn(b.z, b.w) };
    *(uint4*)(g_w1h + i) = *(uint4*)h;
}
__global__ __launch_bounds__(256) void cvt_w2_kernel(const float* __restrict__ w) {
    size_t i = (size_t)(blockIdx.x * blockDim.x + threadIdx.x) * 8;
    float4 a = *(const float4*)(w + i);
    float4 b = *(const float4*)(w + i + 4);
    __half2 h[4] = { __floats2half2_rn(a.x, a.y), __floats2half2_rn(a.z, a.w),
                     __floats2half2_rn(b.x, b.y), __floats2half2_rn(b.z, b.w) };
    *(uint4*)(g_w2h + i) = *(uint4*)h;
}

// ---------------- cp.async WMMA GEMM mainloop (R13 shape) -------------------
// CTA tile 128x128, 8 warps (4m x 2n), warp tile 32x64, KC=64, double-buffered,
// ONE barrier per chunk: wait(ch) -> barrier -> issue(ch+1) -> compute(ch).
// B fragments loaded one at a time to keep live registers under 128.
template<int SK, int NCHUNKS>
__device__ __forceinline__ void gemm_async(
    const __half* __restrict__ Asrc, const int* srcrow,
    const __half* __restrict__ Bsrc, int SN,
    char* DSM, int tid,
    wmma::fragment<wmma::accumulator, 16, 16, 16, float> (&acc)[2][4])
{
    int wid = tid >> 5;
    int warp_m = wid >> 1, warp_n = wid & 1;

    __half* AbP[2] = { (__half*)(DSM + OFF_AB), (__half*)(DSM + OFF_AB) + A_STAGE };
    __half* BbP[2] = { (__half*)(DSM + OFF_BB), (__half*)(DSM + OFF_BB) + B_STAGE };
    uint32_t AbU[2] = { smem_u32(AbP[0]), smem_u32(AbP[1]) };
    uint32_t BbU[2] = { smem_u32(BbP[0]), smem_u32(BbP[1]) };

    // per-thread cp.async mappings: 4 A + 4 B 16B-copies per stage
    const __half* AgB[4]; uint32_t AdO[4];
    const __half* BgB[4]; uint32_t BdO[4];
    #pragma unroll
    for (int l = 0; l < 4; l++) {
        int f = l * 256 + tid;
        int ar = f >> 3, as = f & 7;          // A: 128 rows x 8 segs
        AgB[l] = Asrc + (size_t)srcrow[ar] * SK + as * 8;
        AdO[l] = ar * ROWP + as * 8;
        int br = f >> 4, bs = f & 15;         // B: 64 rows x 16 segs
        BgB[l] = Bsrc + (size_t)br * SN + bs * 8;
        BdO[l] = br * BROWP + bs * 8;
    }

    // prologue: stage 0
    #pragma unroll
    for (int l = 0; l < 4; l++) {
        cpa16(AbU[0] + AdO[l] * 2, AgB[l]);
        cpa16(BbU[0] + BdO[l] * 2, BgB[l]);
    }
    CP_COMMIT();

    for (int ch = 0; ch < NCHUNKS; ch++) {
        int cur = ch & 1;
        CP_WAIT0();
        __syncthreads();
        if (ch + 1 < NCHUNKS) {
            int nxt = cur ^ 1;
            #pragma unroll
            for (int l = 0; l < 4; l++) {
                cpa16(AbU[nxt] + AdO[l] * 2, AgB[l] + (ch + 1) * KC);
                cpa16(BbU[nxt] + BdO[l] * 2, BgB[l] + (size_t)(ch + 1) * KC * SN);
            }
        }
        CP_COMMIT();
        const __half* Ac = AbP[cur];
        const __half* Bc = BbP[cur];
        #pragma unroll
        for (int kf = 0; kf < KC; kf += 16) {
            wmma::fragment<wmma::matrix_a, 16, 16, 16, __half, wmma::row_major> af[2];
            #pragma unroll
            for (int i = 0; i < 2; i++)
                wmma::load_matrix_sync(af[i], Ac + (warp_m * 32 + i * 16) * ROWP + kf, ROWP);
            #pragma unroll
            for (int j = 0; j < 4; j++) {
                wmma::fragment<wmma::matrix_b, 16, 16, 16, __half, wmma::row_major> bf;
                wmma::load_matrix_sync(bf, Bc + kf * BROWP + warp_n * 64 + j * 16, BROWP);
                #pragma unroll
                for (int i = 0; i < 2; i++)
                    wmma::mma_sync(acc[i][j], af[i], bf, acc[i][j]);
            }
        }
    }
    __syncthreads();           // protect smem reuse (epilogue stg aliases A)
}

// ---------------- GEMM1: hbuf = relu(gather(xh) @ w1h[e] + b1[e]) -----------
__global__ __launch_bounds__(256, 2) void gemm1_wmma(const float* __restrict__ b1)
{
    extern __shared__ __align__(16) char DSM[];
    int* toks = (int*)DSM;

    int e = blockIdx.z;
    int cnt = g_cnt[e];
    int m0 = blockIdx.y * 128;
    if (m0 >= cnt) return;
    int n0 = blockIdx.x * 128;
    int base = g_off[e];

    int tid = threadIdx.x, wid = tid >> 5, lane = tid & 31;
    int warp_m = wid >> 1, warp_n = wid & 1;

    if (tid < 128) {
        int m = m0 + tid;
        toks[tid] = g_row_tok[base + ((m < cnt) ? m : 0)];
    }
    __syncthreads();

    wmma::fragment<wmma::accumulator, 16, 16, 16, float> acc[2][4];
    #pragma unroll
    for (int i = 0; i < 2; i++)
        #pragma unroll
        for (int j = 0; j < 4; j++) wmma::fill_fragment(acc[i][j], 0.f);

    gemm_async<DD, DD / KC>(g_xh, toks, g_w1h + (size_t)e * DD * HH + n0, HH,
                            DSM, tid, acc);

    // epilogue: stage via smem (aliases A pipeline region), +bias, relu, fp16
    float* stg = (float*)(DSM + OFF_AB) + wid * 320;
    int erow = lane >> 1, ec8 = (lane & 1) * 8;
    #pragma unroll
    for (int i = 0; i < 2; i++) {
        #pragma unroll
        for (int j = 0; j < 4; j++) {
            wmma::store_matrix_sync(stg, acc[i][j], 20, wmma::mem_row_major);
            __syncwarp();
            int gr = m0 + warp_m * 32 + i * 16 + erow;
            int gc = n0 + warp_n * 64 + j * 16 + ec8;
            if (gr < cnt) {
                __half h[8];
                #pragma unroll
                for (int t2 = 0; t2 < 8; t2++)
                    h[t2] = __float2half_rn(fmaxf(stg[erow * 20 + ec8 + t2]
                                                  + b1[(size_t)e * HH + gc + t2], 0.f));
                *(uint4*)(g_hbuf + (size_t)(base + gr) * HH + gc) = *(uint4*)h;
            }
            __syncwarp();
        }
    }
}

// ---------------- GEMM2: out[tok] += (hbuf @ w2h[e] + b2[e]) * gate ---------
__global__ __launch_bounds__(256, 2) void gemm2_wmma(const float* __restrict__ b2,
                                                     float* __restrict__ out)
{
    extern __shared__ __align__(16) char DSM[];
    int* rows = (int*)DSM;

    int e = blockIdx.z;
    int cnt = g_cnt[e];
    int m0 = blockIdx.y * 128;
    if (m0 >= cnt) return;
    int n0 = blockIdx.x * 128;
    int base = g_off[e];

    int tid = threadIdx.x, wid = tid >> 5, lane = tid & 31;
    int warp_m = wid >> 1, warp_n = wid & 1;

    if (tid < 128) {
        int m = m0 + tid; if (m >= cnt) m = cnt - 1;
        rows[tid] = base + m;
    }
    __syncthreads();

    wmma::fragment<wmma::accumulator, 16, 16, 16, float> acc[2][4];
    #pragma unroll
    for (int i = 0; i < 2; i++)
        #pragma unroll
        for (int j = 0; j < 4; j++) wmma::fill_fragment(acc[i][j], 0.f);

    gemm_async<HH, HH / KC>(g_hbuf, rows, g_w2h + (size_t)e * HH * OO + n0, OO,
                            DSM, tid, acc);

    // epilogue: stage, +bias, * gate, atomic accumulate into out[token]
    float* stg = (float*)(DSM + OFF_AB) + wid * 320;
    int erow = lane >> 1, ec8 = (lane & 1) * 8;
    #pragma unroll
    for (int i = 0; i < 2; i++) {
        #pragma unroll
        for (int j = 0; j < 4; j++) {
            wmma::store_matrix_sync(stg, acc[i][j], 20, wmma::mem_row_major);
            __syncwarp();
            int gr = m0 + warp_m * 32 + i * 16 + erow;
            int gc = n0 + warp_n * 64 + j * 16 + ec8;
            if (gr < cnt) {
                int r = base + gr;
                int tok = g_row_tok[r];
                float gate = g_row_gate[r];
                float* dst = out + (size_t)tok * OO + gc;
                #pragma unroll
                for (int t2 = 0; t2 < 8; t2++)
                    atomicAdd(dst + t2,
                              (stg[erow * 20 + ec8 + t2]
                               + b2[(size_t)e * OO + gc + t2]) * gate);
            }
            __syncwarp();
        }
    }
}

// ---------------- launch ----------------
extern "C" void kernel_launch(void* const* d_in, const int* in_sizes, int n_in,
                              void* d_out, int out_size)
{
    const float* x  = (const float*)d_in[0];
    const float* gw = (const float*)d_in[1];
    const float* gb = (const float*)d_in[2];
    const float* w1 = (const float*)d_in[3];
    const float* b1 = (const float*)d_in[4];
    const float* w2 = (const float*)d_in[5];
    const float* b2 = (const float*)d_in[6];
    float* out = (float*)d_out;

    static int attr_done = 0;
    if (!attr_done) {
        cudaFuncSetAttribute(gemm1_wmma, cudaFuncAttributeMaxDynamicSharedMemorySize, SMEM_DYN);
        cudaFuncSetAttribute(gemm2_wmma, cudaFuncAttributeMaxDynamicSharedMemorySize, SMEM_DYN);
        attr_done = 1;
    }

    zero_kernel<<<1, 32>>>();
    gate_kernel<<<TB, 256>>>(x, gw, gb);
    offsets_kernel<<<1, 1>>>();
    scatter_kernel<<<TB / 256, 256>>>();
    cvt_w1_kernel<<<NE * DD * HH / 8 / 256, 256>>>(w1);
    cvt_w2_kernel<<<NE * HH * OO / 8 / 256, 256>>>(w2);
    zero_out_kernel<<<TB * OO / 4 / 256, 256>>>(out);
    gemm1_wmma<<<dim3(HH / 128, NR / 128, NE), 256, SMEM_DYN>>>(b1);
    gemm2_wmma<<<dim3(OO / 128, NR / 128, NE), 256, SMEM_DYN>>>(b2, out);
}

// round 16
// speedup vs baseline: 1.0389x; 1.0027x over previous
#include <cuda_runtime.h>
#include <cuda_fp16.h>
#include <mma.h>
#include <math.h>
#include <stdint.h>

using namespace nvcuda;

// Problem constants: B=4, S=2048, D=1024, H=2048, O=1024, E=8, K=2
#define TB   8192
#define DD   1024
#define HH   2048
#define OO   1024
#define NE   8
#define NR   16384

// ---------------- scratch (__device__ globals; referenced ONLY inside kernels)
__device__ int    g_cnt[NE];
__device__ int    g_off[NE];
__device__ int    g_tok_e[TB * 2];
__device__ float  g_tok_p[TB * 2];
__device__ int    g_row_tok[NR];
__device__ float  g_row_gate[NR];
__device__ __half g_xh[(size_t)TB * DD];        // 16.8 MB x fp16
__device__ __half g_w1h[(size_t)NE * DD * HH];  // 33.5 MB w1 fp16 [E][D][H]
__device__ __half g_w2h[(size_t)NE * HH * OO];  // 33.5 MB w2 fp16 [E][H][O]
__device__ __half g_hbuf[(size_t)NR * HH];      // 67 MB hidden activations fp16

// smem geometry: CTA tile 128x128, KC=64 (R13-proven)
#define KC     64
#define ROWP   72            // A row pitch (halves): 64 data + 8 pad
#define BROWP  136           // B row pitch (halves): 128 data + 8 pad
#define A_STAGE (128 * ROWP)            // 9216 halves = 18432 B
#define B_STAGE (KC * BROWP)            // 8704 halves  = 17408 B
#define OFF_AB   1024
#define OFF_BB   (OFF_AB + 2 * A_STAGE * 2)
#define SMEM_DYN (OFF_BB + 2 * B_STAGE * 2)   // 72704 B

// ---------------- cp.async helpers ----------------
__device__ __forceinline__ uint32_t smem_u32(const void* p) {
    uint32_t a;
    asm("{ .reg .u64 t; cvta.to.shared.u64 t, %1; cvt.u32.u64 %0, t; }" : "=r"(a) : "l"(p));
    return a;
}
__device__ __forceinline__ void cpa16(uint32_t dst, const void* src) {
    asm volatile("cp.async.cg.shared.global [%0], [%1], 16;" :: "r"(dst), "l"(src));
}
#define CP_COMMIT() asm volatile("cp.async.commit_group;" ::: "memory")
#define CP_WAIT0()  asm volatile("cp.async.wait_group 0;" ::: "memory")

// ---------------- launch 0: w1 convert + zero routing counters --------------
__global__ __launch_bounds__(256) void cvt_w1_kernel(const float* __restrict__ w) {
    if (blockIdx.x == 0 && threadIdx.x < NE) g_cnt[threadIdx.x] = 0;
    size_t i = (size_t)(blockIdx.x * blockDim.x + threadIdx.x) * 8;
    float4 a = *(const float4*)(w + i);
    float4 b = *(const float4*)(w + i + 4);
    __half2 h[4] = { __floats2half2_rn(a.x, a.y), __floats2half2_rn(a.z, a.w),
                     __floats2half2_rn(b.x, b.y), __floats2half2_rn(b.z, b.w) };
    *(uint4*)(g_w1h + i) = *(uint4*)h;
}

// ---------------- launch 1: gate + fused x fp32->fp16 -----------------------
__global__ __launch_bounds__(256) void gate_kernel(
    const float* __restrict__ x, const float* __restrict__ gw, const float* __restrict__ gb)
{
    int t = blockIdx.x, tid = threadIdx.x;
    int w = tid >> 5, lane = tid & 31;
    const float* xr = x + (size_t)t * DD;
    const float* gr = gw + (size_t)w * DD;
    float s = 0.f;
    #pragma unroll 8
    for (int j = lane; j < DD; j += 32) s += xr[j] * gr[j];
    #pragma unroll
    for (int o = 16; o > 0; o >>= 1) s += __shfl_xor_sync(0xFFFFFFFFu, s, o);
    __shared__ float lg[NE];
    if (lane == 0) lg[w] = s + gb[w];

    // fused conversion: 4 floats per thread
    {
        int j = tid * 4;
        float4 v = *(const float4*)(xr + j);
        __half2 h0 = __floats2half2_rn(v.x, v.y);
        __half2 h1 = __floats2half2_rn(v.z, v.w);
        uint2 u;
        u.x = *(uint32_t*)&h0; u.y = *(uint32_t*)&h1;
        *(uint2*)(g_xh + (size_t)t * DD + j) = u;
    }
    __syncthreads();
    if (tid == 0) {
        float mx = lg[0];
        #pragma unroll
        for (int e = 1; e < NE; e++) mx = fmaxf(mx, lg[e]);
        float ex[NE]; float den = 0.f;
        #pragma unroll
        for (int e = 0; e < NE; e++) { ex[e] = expf(lg[e] - mx); den += ex[e]; }
        int i0 = 0;
        #pragma unroll
        for (int e = 1; e < NE; e++) if (lg[e] > lg[i0]) i0 = e;
        int i1 = (i0 == 0) ? 1 : 0;
        #pragma unroll
        for (int e = 0; e < NE; e++) if (e != i0 && e != i1 && lg[e] > lg[i1]) i1 = e;
        float inv = 1.f / den;
        g_tok_e[t * 2 + 0] = i0; g_tok_p[t * 2 + 0] = ex[i0] * inv;
        g_tok_e[t * 2 + 1] = i1; g_tok_p[t * 2 + 1] = ex[i1] * inv;
        atomicAdd(&g_cnt[i0], 1);
        atomicAdd(&g_cnt[i1], 1);
    }
}

// ---------------- launch 2: fused offsets + scatter (single block) ----------
__global__ __launch_bounds__(1024) void scatter1b_kernel() {
    __shared__ int soff[NE];
    __shared__ int sfill[NE];
    int tid = threadIdx.x;
    if (tid == 0) {
        int s = 0;
        #pragma unroll
        for (int e = 0; e < NE; e++) { soff[e] = s; g_off[e] = s; s += g_cnt[e]; }
    }
    if (tid < NE) sfill[tid] = 0;
    __syncthreads();
    for (int t = tid; t < TB; t += 1024) {
        #pragma unroll
        for (int k = 0; k < 2; k++) {
            int e = g_tok_e[t * 2 + k];
            int pos = atomicAdd(&sfill[e], 1);
            int r = soff[e] + pos;
            g_row_tok[r] = t;
            g_row_gate[r] = g_tok_p[t * 2 + k];
        }
    }
}

// ---------------- late converts / zero-out ----------------------------------
__global__ __launch_bounds__(256) void cvt_w2_kernel(const float* __restrict__ w) {
    size_t i = (size_t)(blockIdx.x * blockDim.x + threadIdx.x) * 8;
    float4 a = *(const float4*)(w + i);
    float4 b = *(const float4*)(w + i + 4);
    __half2 h[4] = { __floats2half2_rn(a.x, a.y), __floats2half2_rn(a.z, a.w),
                     __floats2half2_rn(b.x, b.y), __floats2half2_rn(b.z, b.w) };
    *(uint4*)(g_w2h + i) = *(uint4*)h;
}

__global__ __launch_bounds__(256) void zero_out_kernel(float* __restrict__ out) {
    size_t i = (size_t)(blockIdx.x * blockDim.x + threadIdx.x) * 4;
    *(float4*)(out + i) = make_float4(0.f, 0.f, 0.f, 0.f);
}

// ---------------- cp.async WMMA GEMM mainloop (R13 shape, unchanged) --------
// CTA tile 128x128, 8 warps (4m x 2n), warp tile 32x64, KC=64, double-buffered,
// ONE barrier per chunk: wait(ch) -> barrier -> issue(ch+1) -> compute(ch).
template<int SK, int NCHUNKS>
__device__ __forceinline__ void gemm_async(
    const __half* __restrict__ Asrc, const int* srcrow,
    const __half* __restrict__ Bsrc, int SN,
    char* DSM, int tid,
    wmma::fragment<wmma::accumulator, 16, 16, 16, float> (&acc)[2][4])
{
    int wid = tid >> 5;
    int warp_m = wid >> 1, warp_n = wid & 1;

    __half* AbP[2] = { (__half*)(DSM + OFF_AB), (__half*)(DSM + OFF_AB) + A_STAGE };
    __half* BbP[2] = { (__half*)(DSM + OFF_BB), (__half*)(DSM + OFF_BB) + B_STAGE };
    uint32_t AbU[2] = { smem_u32(AbP[0]), smem_u32(AbP[1]) };
    uint32_t BbU[2] = { smem_u32(BbP[0]), smem_u32(BbP[1]) };

    const __half* AgB[4]; uint32_t AdO[4];
    const __half* BgB[4]; uint32_t BdO[4];
    #pragma unroll
    for (int l = 0; l < 4; l++) {
        int f = l * 256 + tid;
        int ar = f >> 3, as = f & 7;          // A: 128 rows x 8 segs
        AgB[l] = Asrc + (size_t)srcrow[ar] * SK + as * 8;
        AdO[l] = ar * ROWP + as * 8;
        int br = f >> 4, bs = f & 15;         // B: 64 rows x 16 segs
        BgB[l] = Bsrc + (size_t)br * SN + bs * 8;
        BdO[l] = br * BROWP + bs * 8;
    }

    #pragma unroll
    for (int l = 0; l < 4; l++) {
        cpa16(AbU[0] + AdO[l] * 2, AgB[l]);
        cpa16(BbU[0] + BdO[l] * 2, BgB[l]);
    }
    CP_COMMIT();

    for (int ch = 0; ch < NCHUNKS; ch++) {
        int cur = ch & 1;
        CP_WAIT0();
        __syncthreads();
        if (ch + 1 < NCHUNKS) {
            int nxt = cur ^ 1;
            #pragma unroll
            for (int l = 0; l < 4; l++) {
                cpa16(AbU[nxt] + AdO[l] * 2, AgB[l] + (ch + 1) * KC);
                cpa16(BbU[nxt] + BdO[l] * 2, BgB[l] + (size_t)(ch + 1) * KC * SN);
            }
        }
        CP_COMMIT();
        const __half* Ac = AbP[cur];
        const __half* Bc = BbP[cur];
        #pragma unroll
        for (int kf = 0; kf < KC; kf += 16) {
            wmma::fragment<wmma::matrix_a, 16, 16, 16, __half, wmma::row_major> af[2];
            #pragma unroll
            for (int i = 0; i < 2; i++)
                wmma::load_matrix_sync(af[i], Ac + (warp_m * 32 + i * 16) * ROWP + kf, ROWP);
            #pragma unroll
            for (int j = 0; j < 4; j++) {
                wmma::fragment<wmma::matrix_b, 16, 16, 16, __half, wmma::row_major> bf;
                wmma::load_matrix_sync(bf, Bc + kf * BROWP + warp_n * 64 + j * 16, BROWP);
                #pragma unroll
                for (int i = 0; i < 2; i++)
                    wmma::mma_sync(acc[i][j], af[i], bf, acc[i][j]);
            }
        }
    }
    __syncthreads();           // protect smem reuse (epilogue stg aliases A)
}

// ---------------- GEMM1: hbuf = relu(gather(xh) @ w1h[e] + b1[e]) -----------
__global__ __launch_bounds__(256) void gemm1_wmma(const float* __restrict__ b1)
{
    extern __shared__ __align__(16) char DSM[];
    int* toks = (int*)DSM;

    int e = blockIdx.z;
    int cnt = g_cnt[e];
    int m0 = blockIdx.y * 128;
    if (m0 >= cnt) return;
    int n0 = blockIdx.x * 128;
    int base = g_off[e];

    int tid = threadIdx.x, wid = tid >> 5, lane = tid & 31;
    int warp_m = wid >> 1, warp_n = wid & 1;

    if (tid < 128) {
        int m = m0 + tid;
        toks[tid] = g_row_tok[base + ((m < cnt) ? m : 0)];
    }
    __syncthreads();

    wmma::fragment<wmma::accumulator, 16, 16, 16, float> acc[2][4];
    #pragma unroll
    for (int i = 0; i < 2; i++)
        #pragma unroll
        for (int j = 0; j < 4; j++) wmma::fill_fragment(acc[i][j], 0.f);

    gemm_async<DD, DD / KC>(g_xh, toks, g_w1h + (size_t)e * DD * HH + n0, HH,
                            DSM, tid, acc);

    float* stg = (float*)(DSM + OFF_AB) + wid * 320;
    int erow = lane >> 1, ec8 = (lane & 1) * 8;
    #pragma unroll
    for (int i = 0; i < 2; i++) {
        #pragma unroll
        for (int j = 0; j < 4; j++) {
            wmma::store_matrix_sync(stg, acc[i][j], 20, wmma::mem_row_major);
            __syncwarp();
            int gr = m0 + warp_m * 32 + i * 16 + erow;
            int gc = n0 + warp_n * 64 + j * 16 + ec8;
            if (gr < cnt) {
                __half h[8];
                #pragma unroll
                for (int t2 = 0; t2 < 8; t2++)
                    h[t2] = __float2half_rn(fmaxf(stg[erow * 20 + ec8 + t2]
                                                  + b1[(size_t)e * HH + gc + t2], 0.f));
                *(uint4*)(g_hbuf + (size_t)(base + gr) * HH + gc) = *(uint4*)h;
            }
            __syncwarp();
        }
    }
}

// ---------------- GEMM2: out[tok] += (hbuf @ w2h[e] + b2[e]) * gate ---------
__global__ __launch_bounds__(256) void gemm2_wmma(const float* __restrict__ b2,
                                                  float* __restrict__ out)
{
    extern __shared__ __align__(16) char DSM[];
    int* rows = (int*)DSM;

    int e = blockIdx.z;
    int cnt = g_cnt[e];
    int m0 = blockIdx.y * 128;
    if (m0 >= cnt) return;
    int n0 = blockIdx.x * 128;
    int base = g_off[e];

    int tid = threadIdx.x, wid = tid >> 5, lane = tid & 31;
    int warp_m = wid >> 1, warp_n = wid & 1;

    if (tid < 128) {
        int m = m0 + tid; if (m >= cnt) m = cnt - 1;
        rows[tid] = base + m;
    }
    __syncthreads();

    wmma::fragment<wmma::accumulator, 16, 16, 16, float> acc[2][4];
    #pragma unroll
    for (int i = 0; i < 2; i++)
        #pragma unroll
        for (int j = 0; j < 4; j++) wmma::fill_fragment(acc[i][j], 0.f);

    gemm_async<HH, HH / KC>(g_hbuf, rows, g_w2h + (size_t)e * HH * OO + n0, OO,
                            DSM, tid, acc);

    float* stg = (float*)(DSM + OFF_AB) + wid * 320;
    int erow = lane >> 1, ec8 = (lane & 1) * 8;
    #pragma unroll
    for (int i = 0; i < 2; i++) {
        #pragma unroll
        for (int j = 0; j < 4; j++) {
            wmma::store_matrix_sync(stg, acc[i][j], 20, wmma::mem_row_major);
            __syncwarp();
            int gr = m0 + warp_m * 32 + i * 16 + erow;
            int gc = n0 + warp_n * 64 + j * 16 + ec8;
            if (gr < cnt) {
                int r = base + gr;
                int tok = g_row_tok[r];
                float gate = g_row_gate[r];
                float* dst = out + (size_t)tok * OO + gc;
                #pragma unroll
                for (int t2 = 0; t2 < 8; t2++)
                    atomicAdd(dst + t2,
                              (stg[erow * 20 + ec8 + t2]
                               + b2[(size_t)e * OO + gc + t2]) * gate);
            }
            __syncwarp();
        }
    }
}

// ---------------- launch ----------------
extern "C" void kernel_launch(void* const* d_in, const int* in_sizes, int n_in,
                              void* d_out, int out_size)
{
    const float* x  = (const float*)d_in[0];
    const float* gw = (const float*)d_in[1];
    const float* gb = (const float*)d_in[2];
    const float* w1 = (const float*)d_in[3];
    const float* b1 = (const float*)d_in[4];
    const float* w2 = (const float*)d_in[5];
    const float* b2 = (const float*)d_in[6];
    float* out = (float*)d_out;

    static int attr_done = 0;
    if (!attr_done) {
        cudaFuncSetAttribute(gemm1_wmma, cudaFuncAttributeMaxDynamicSharedMemorySize, SMEM_DYN);
        cudaFuncSetAttribute(gemm2_wmma, cudaFuncAttributeMaxDynamicSharedMemorySize, SMEM_DYN);
        attr_done = 1;
    }

    // launch index:                                     (profiled slot = #3)
    cvt_w1_kernel<<<NE * DD * HH / 8 / 256, 256>>>(w1);        // 0 (+zero cnt)
    gate_kernel<<<TB, 256>>>(x, gw, gb);                       // 1 (+cvt x)
    scatter1b_kernel<<<1, 1024>>>();                           // 2 (offsets+scatter)
    gemm1_wmma<<<dim3(HH / 128, NR / 128, NE), 256, SMEM_DYN>>>(b1);  // 3 <- ncu
    cvt_w2_kernel<<<NE * HH * OO / 8 / 256, 256>>>(w2);        // 4
    zero_out_kernel<<<TB * OO / 4 / 256, 256>>>(out);          // 5
    gemm2_wmma<<<dim3(OO / 128, NR / 128, NE), 256, SMEM_DYN>>>(b2, out); // 6
}

// round 17
// speedup vs baseline: 1.0630x; 1.0232x over previous
#include <cuda_runtime.h>
#include <cuda_fp16.h>
#include <mma.h>
#include <math.h>
#include <stdint.h>

using namespace nvcuda;

// Problem constants: B=4, S=2048, D=1024, H=2048, O=1024, E=8, K=2
#define TB   8192
#define DD   1024
#define HH   2048
#define OO   1024
#define NE   8
#define NR   16384
#define MAXTILES 144

// ---------------- scratch (__device__ globals; referenced ONLY inside kernels)
__device__ int    g_cnt[NE];
__device__ int    g_off[NE];
__device__ int    g_tok_e[TB * 2];
__device__ float  g_tok_p[TB * 2];
__device__ int    g_row_tok[NR];
__device__ float  g_row_gate[NR];
__device__ int    g_tile_e[MAXTILES];
__device__ int    g_tile_m0[MAXTILES];
__device__ int    g_ntiles;
__device__ __half g_xh[(size_t)TB * DD];        // 16.8 MB x fp16
__device__ __half g_w1h[(size_t)NE * DD * HH];  // 33.5 MB w1 fp16 [E][D][H]
__device__ __half g_w2h[(size_t)NE * HH * OO];  // 33.5 MB w2 fp16 [E][H][O]
__device__ __half g_hbuf[(size_t)NR * HH];      // 67 MB hidden activations fp16

// smem geometry: CTA tile 128x128, KC=64 (R13-proven)
#define KC     64
#define ROWP   72            // A row pitch (halves): 64 data + 8 pad
#define BROWP  136           // B row pitch (halves): 128 data + 8 pad
#define A_STAGE (128 * ROWP)            // 9216 halves = 18432 B
#define B_STAGE (KC * BROWP)            // 8704 halves  = 17408 B
#define OFF_AB   1024
#define OFF_BB   (OFF_AB + 2 * A_STAGE * 2)
#define SMEM_DYN (OFF_BB + 2 * B_STAGE * 2)   // 72704 B

// ---------------- cp.async helpers ----------------
__device__ __forceinline__ uint32_t smem_u32(const void* p) {
    uint32_t a;
    asm("{ .reg .u64 t; cvta.to.shared.u64 t, %1; cvt.u32.u64 %0, t; }" : "=r"(a) : "l"(p));
    return a;
}
__device__ __forceinline__ void cpa16(uint32_t dst, const void* src) {
    asm volatile("cp.async.cg.shared.global [%0], [%1], 16;" :: "r"(dst), "l"(src));
}
#define CP_COMMIT() asm volatile("cp.async.commit_group;" ::: "memory")
#define CP_WAIT0()  asm volatile("cp.async.wait_group 0;" ::: "memory")

// ---------------- launch 0: w1 convert + zero routing counters --------------
__global__ __launch_bounds__(256) void cvt_w1_kernel(const float* __restrict__ w) {
    if (blockIdx.x == 0 && threadIdx.x < NE) g_cnt[threadIdx.x] = 0;
    size_t i = (size_t)(blockIdx.x * blockDim.x + threadIdx.x) * 8;
    float4 a = *(const float4*)(w + i);
    float4 b = *(const float4*)(w + i + 4);
    __half2 h[4] = { __floats2half2_rn(a.x, a.y), __floats2half2_rn(a.z, a.w),
                     __floats2half2_rn(b.x, b.y), __floats2half2_rn(b.z, b.w) };
    *(uint4*)(g_w1h + i) = *(uint4*)h;
}

// ---------------- launch 1: gate + fused x fp32->fp16 -----------------------
__global__ __launch_bounds__(256) void gate_kernel(
    const float* __restrict__ x, const float* __restrict__ gw, const float* __restrict__ gb)
{
    int t = blockIdx.x, tid = threadIdx.x;
    int w = tid >> 5, lane = tid & 31;
    const float* xr = x + (size_t)t * DD;
    const float* gr = gw + (size_t)w * DD;
    float s = 0.f;
    #pragma unroll 8
    for (int j = lane; j < DD; j += 32) s += xr[j] * gr[j];
    #pragma unroll
    for (int o = 16; o > 0; o >>= 1) s += __shfl_xor_sync(0xFFFFFFFFu, s, o);
    __shared__ float lg[NE];
    if (lane == 0) lg[w] = s + gb[w];

    {
        int j = tid * 4;
        float4 v = *(const float4*)(xr + j);
        __half2 h0 = __floats2half2_rn(v.x, v.y);
        __half2 h1 = __floats2half2_rn(v.z, v.w);
        uint2 u;
        u.x = *(uint32_t*)&h0; u.y = *(uint32_t*)&h1;
        *(uint2*)(g_xh + (size_t)t * DD + j) = u;
    }
    __syncthreads();
    if (tid == 0) {
        float mx = lg[0];
        #pragma unroll
        for (int e = 1; e < NE; e++) mx = fmaxf(mx, lg[e]);
        float ex[NE]; float den = 0.f;
        #pragma unroll
        for (int e = 0; e < NE; e++) { ex[e] = expf(lg[e] - mx); den += ex[e]; }
        int i0 = 0;
        #pragma unroll
        for (int e = 1; e < NE; e++) if (lg[e] > lg[i0]) i0 = e;
        int i1 = (i0 == 0) ? 1 : 0;
        #pragma unroll
        for (int e = 0; e < NE; e++) if (e != i0 && e != i1 && lg[e] > lg[i1]) i1 = e;
        float inv = 1.f / den;
        g_tok_e[t * 2 + 0] = i0; g_tok_p[t * 2 + 0] = ex[i0] * inv;
        g_tok_e[t * 2 + 1] = i1; g_tok_p[t * 2 + 1] = ex[i1] * inv;
        atomicAdd(&g_cnt[i0], 1);
        atomicAdd(&g_cnt[i1], 1);
    }
}

// ---------------- launch 2: offsets + scatter + tile table (single block) ---
__global__ __launch_bounds__(1024) void scatter1b_kernel() {
    __shared__ int soff[NE];
    __shared__ int sfill[NE];
    int tid = threadIdx.x;
    if (tid == 0) {
        int s = 0, nt = 0;
        #pragma unroll
        for (int e = 0; e < NE; e++) {
            soff[e] = s; g_off[e] = s;
            for (int m0 = 0; m0 < g_cnt[e]; m0 += 128) {
                g_tile_e[nt] = e; g_tile_m0[nt] = m0; nt++;
            }
            s += g_cnt[e];
        }
        g_ntiles = nt;
    }
    if (tid < NE) sfill[tid] = 0;
    __syncthreads();
    for (int t = tid; t < TB; t += 1024) {
        #pragma unroll
        for (int k = 0; k < 2; k++) {
            int e = g_tok_e[t * 2 + k];
            int pos = atomicAdd(&sfill[e], 1);
            int r = soff[e] + pos;
            g_row_tok[r] = t;
            g_row_gate[r] = g_tok_p[t * 2 + k];
        }
    }
}

// ---------------- late converts / zero-out ----------------------------------
__global__ __launch_bounds__(256) void cvt_w2_kernel(const float* __restrict__ w) {
    size_t i = (size_t)(blockIdx.x * blockDim.x + threadIdx.x) * 8;
    float4 a = *(const float4*)(w + i);
    float4 b = *(const float4*)(w + i + 4);
    __half2 h[4] = { __floats2half2_rn(a.x, a.y), __floats2half2_rn(a.z, a.w),
                     __floats2half2_rn(b.x, b.y), __floats2half2_rn(b.z, b.w) };
    *(uint4*)(g_w2h + i) = *(uint4*)h;
}

__global__ __launch_bounds__(256) void zero_out_kernel(float* __restrict__ out) {
    size_t i = (size_t)(blockIdx.x * blockDim.x + threadIdx.x) * 4;
    *(float4*)(out + i) = make_float4(0.f, 0.f, 0.f, 0.f);
}

// ---------------- cp.async WMMA GEMM mainloop (R13 inner loop restored) -----
// CTA tile 128x128, 8 warps (4m x 2n), warp tile 32x64, KC=64, double-buffered,
// ONE barrier per chunk; batched af[2] + bf[4] fragment loads (4 LDSMs in
// flight cover shared-memory latency).
template<int SK, int NCHUNKS>
__device__ __forceinline__ void gemm_async(
    const __half* __restrict__ Asrc, const int* srcrow,
    const __half* __restrict__ Bsrc, int SN,
    char* DSM, int tid,
    wmma::fragment<wmma::accumulator, 16, 16, 16, float> (&acc)[2][4])
{
    int wid = tid >> 5;
    int warp_m = wid >> 1, warp_n = wid & 1;

    __half* AbP[2] = { (__half*)(DSM + OFF_AB), (__half*)(DSM + OFF_AB) + A_STAGE };
    __half* BbP[2] = { (__half*)(DSM + OFF_BB), (__half*)(DSM + OFF_BB) + B_STAGE };
    uint32_t AbU[2] = { smem_u32(AbP[0]), smem_u32(AbP[1]) };
    uint32_t BbU[2] = { smem_u32(BbP[0]), smem_u32(BbP[1]) };

    const __half* AgB[4]; uint32_t AdO[4];
    const __half* BgB[4]; uint32_t BdO[4];
    #pragma unroll
    for (int l = 0; l < 4; l++) {
        int f = l * 256 + tid;
        int ar = f >> 3, as = f & 7;          // A: 128 rows x 8 segs
        AgB[l] = Asrc + (size_t)srcrow[ar] * SK + as * 8;
        AdO[l] = ar * ROWP + as * 8;
        int br = f >> 4, bs = f & 15;         // B: 64 rows x 16 segs
        BgB[l] = Bsrc + (size_t)br * SN + bs * 8;
        BdO[l] = br * BROWP + bs * 8;
    }

    #pragma unroll
    for (int l = 0; l < 4; l++) {
        cpa16(AbU[0] + AdO[l] * 2, AgB[l]);
        cpa16(BbU[0] + BdO[l] * 2, BgB[l]);
    }
    CP_COMMIT();

    for (int ch = 0; ch < NCHUNKS; ch++) {
        int cur = ch & 1;
        CP_WAIT0();
        __syncthreads();
        if (ch + 1 < NCHUNKS) {
            int nxt = cur ^ 1;
            #pragma unroll
            for (int l = 0; l < 4; l++) {
                cpa16(AbU[nxt] + AdO[l] * 2, AgB[l] + (ch + 1) * KC);
                cpa16(BbU[nxt] + BdO[l] * 2, BgB[l] + (size_t)(ch + 1) * KC * SN);
            }
        }
        CP_COMMIT();
        const __half* Ac = AbP[cur];
        const __half* Bc = BbP[cur];
        #pragma unroll
        for (int kf = 0; kf < KC; kf += 16) {
            wmma::fragment<wmma::matrix_a, 16, 16, 16, __half, wmma::row_major> af[2];
            wmma::fragment<wmma::matrix_b, 16, 16, 16, __half, wmma::row_major> bf[4];
            #pragma unroll
            for (int i = 0; i < 2; i++)
                wmma::load_matrix_sync(af[i], Ac + (warp_m * 32 + i * 16) * ROWP + kf, ROWP);
            #pragma unroll
            for (int j = 0; j < 4; j++)
                wmma::load_matrix_sync(bf[j], Bc + kf * BROWP + warp_n * 64 + j * 16, BROWP);
            #pragma unroll
            for (int i = 0; i < 2; i++)
                #pragma unroll
                for (int j = 0; j < 4; j++)
                    wmma::mma_sync(acc[i][j], af[i], bf[j], acc[i][j]);
        }
    }
    __syncthreads();           // protect smem reuse (epilogue stg aliases A)
}

// ---------------- GEMM1: hbuf = relu(gather(xh) @ w1h[e] + b1[e]) -----------
__global__ __launch_bounds__(256) void gemm1_wmma(const float* __restrict__ b1)
{
    extern __shared__ __align__(16) char DSM[];
    int* toks = (int*)DSM;

    int ti = blockIdx.y;
    if (ti >= g_ntiles) return;
    int e = g_tile_e[ti];
    int m0 = g_tile_m0[ti];
    int cnt = g_cnt[e];
    int n0 = blockIdx.x * 128;
    int base = g_off[e];

    int tid = threadIdx.x, wid = tid >> 5, lane = tid & 31;
    int warp_m = wid >> 1, warp_n = wid & 1;

    if (tid < 128) {
        int m = m0 + tid;
        toks[tid] = g_row_tok[base + ((m < cnt) ? m : 0)];
    }
    __syncthreads();

    wmma::fragment<wmma::accumulator, 16, 16, 16, float> acc[2][4];
    #pragma unroll
    for (int i = 0; i < 2; i++)
        #pragma unroll
        for (int j = 0; j < 4; j++) wmma::fill_fragment(acc[i][j], 0.f);

    gemm_async<DD, DD / KC>(g_xh, toks, g_w1h + (size_t)e * DD * HH + n0, HH,
                            DSM, tid, acc);

    float* stg = (float*)(DSM + OFF_AB) + wid * 320;
    int erow = lane >> 1, ec8 = (lane & 1) * 8;
    #pragma unroll
    for (int i = 0; i < 2; i++) {
        #pragma unroll
        for (int j = 0; j < 4; j++) {
            wmma::store_matrix_sync(stg, acc[i][j], 20, wmma::mem_row_major);
            __syncwarp();
            int gr = m0 + warp_m * 32 + i * 16 + erow;
            int gc = n0 + warp_n * 64 + j * 16 + ec8;
            if (gr < cnt) {
                __half h[8];
                #pragma unroll
                for (int t2 = 0; t2 < 8; t2++)
                    h[t2] = __float2half_rn(fmaxf(stg[erow * 20 + ec8 + t2]
                                                  + b1[(size_t)e * HH + gc + t2], 0.f));
                *(uint4*)(g_hbuf + (size_t)(base + gr) * HH + gc) = *(uint4*)h;
            }
            __syncwarp();
        }
    }
}

// ---------------- GEMM2: out[tok] += (hbuf @ w2h[e] + b2[e]) * gate ---------
__global__ __launch_bounds__(256) void gemm2_wmma(const float* __restrict__ b2,
                                                  float* __restrict__ out)
{
    extern __shared__ __align__(16) char DSM[];
    int* rows = (int*)DSM;

    int ti = blockIdx.y;
    if (ti >= g_ntiles) return;
    int e = g_tile_e[ti];
    int m0 = g_tile_m0[ti];
    int cnt = g_cnt[e];
    int n0 = blockIdx.x * 128;
    int base = g_off[e];

    int tid = threadIdx.x, wid = tid >> 5, lane = tid & 31;
    int warp_m = wid >> 1, warp_n = wid & 1;

    if (tid < 128) {
        int m = m0 + tid; if (m >= cnt) m = cnt - 1;
        rows[tid] = base + m;
    }
    __syncthreads();

    wmma::fragment<wmma::accumulator, 16, 16, 16, float> acc[2][4];
    #pragma unroll
    for (int i = 0; i < 2; i++)
        #pragma unroll
        for (int j = 0; j < 4; j++) wmma::fill_fragment(acc[i][j], 0.f);

    gemm_async<HH, HH / KC>(g_hbuf, rows, g_w2h + (size_t)e * HH * OO + n0, OO,
                            DSM, tid, acc);

    float* stg = (float*)(DSM + OFF_AB) + wid * 320;
    int erow = lane >> 1, ec8 = (lane & 1) * 8;
    #pragma unroll
    for (int i = 0; i < 2; i++) {
        #pragma unroll
        for (int j = 0; j < 4; j++) {
            wmma::store_matrix_sync(stg, acc[i][j], 20, wmma::mem_row_major);
            __syncwarp();
            int gr = m0 + warp_m * 32 + i * 16 + erow;
            int gc = n0 + warp_n * 64 + j * 16 + ec8;
            if (gr < cnt) {
                int r = base + gr;
                int tok = g_row_tok[r];
                float gate = g_row_gate[r];
                float* dst = out + (size_t)tok * OO + gc;
                #pragma unroll
                for (int t2 = 0; t2 < 8; t2++)
                    atomicAdd(dst + t2,
                              (stg[erow * 20 + ec8 + t2]
                               + b2[(size_t)e * OO + gc + t2]) * gate);
            }
            __syncwarp();
        }
    }
}

// ---------------- launch ----------------
extern "C" void kernel_launch(void* const* d_in, const int* in_sizes, int n_in,
                              void* d_out, int out_size)
{
    const float* x  = (const float*)d_in[0];
    const float* gw = (const float*)d_in[1];
    const float* gb = (const float*)d_in[2];
    const float* w1 = (const float*)d_in[3];
    const float* b1 = (const float*)d_in[4];
    const float* w2 = (const float*)d_in[5];
    const float* b2 = (const float*)d_in[6];
    float* out = (float*)d_out;

    static int attr_done = 0;
    if (!attr_done) {
        cudaFuncSetAttribute(gemm1_wmma, cudaFuncAttributeMaxDynamicSharedMemorySize, SMEM_DYN);
        cudaFuncSetAttribute(gemm2_wmma, cudaFuncAttributeMaxDynamicSharedMemorySize, SMEM_DYN);
        attr_done = 1;
    }

    // launch index:                                     (profiled slot = #3)
    cvt_w1_kernel<<<NE * DD * HH / 8 / 256, 256>>>(w1);        // 0 (+zero cnt)
    gate_kernel<<<TB, 256>>>(x, gw, gb);                       // 1 (+cvt x)
    scatter1b_kernel<<<1, 1024>>>();                           // 2 (+tile table)
    gemm1_wmma<<<dim3(HH / 128, MAXTILES - 8), 256, SMEM_DYN>>>(b1);  // 3 <- ncu
    cvt_w2_kernel<<<NE * HH * OO / 8 / 256, 256>>>(w2);        // 4
    zero_out_kernel<<<TB * OO / 4 / 256, 256>>>(out);          // 5
    gemm2_wmma<<<dim3(OO / 128, MAXTILES - 8), 256, SMEM_DYN>>>(b2, out); // 6
}